// round 16
// baseline (speedup 1.0000x reference)
#include <cuda_runtime.h>
#include <cuda_fp16.h>
#include <cstdint>

typedef unsigned u32;

#define NAGENT 8
#define BATCH  32768
#define BM     128

// ---- scratch: pre-swizzled fp16 weights ----
// per agent: L1 (128 rows) off 0, L2 off 32768, L3 (64 rows) off 65536; stride 81920
__device__ __align__(16) unsigned char g_w[8 * 81920];
__device__ __align__(16) unsigned char g_ax[48 * 256];   // aux: Wc1^T rows 0-31, Ws1 row 32, pad

// ---- smem byte offsets (one 512-thread CTA per SM, ~173.5 KB) ----
#define RA    0          // plane P0: 128 rows x 256B fp16 (32KB)
#define RB    32768      // plane P1 (32KB)
#define RST   65536      // f32 states staging (128 x 512B = 64KB)
#define RW    131072     // weights, 176 rows x 256B = 45056 (aux rows 128-175 persist)
#define SGOFF 176128     // gate per row (128 f32)
#define SREDO 176640     // csum partials (128 rows x 2 slots)
#define SMEM_TOTAL 177664

// ======================= helpers =======================
__device__ __forceinline__ u32 smem_u32(const void* p) {
    u32 a; asm("{ .reg .u64 t; cvta.to.shared.u64 t, %1; cvt.u32.u64 %0, t; }" : "=r"(a) : "l"(p));
    return a;
}
__device__ __forceinline__ void cp16(u32 dst, const void* src) {
    asm volatile("cp.async.cg.shared.global [%0], [%1], 16;" :: "r"(dst), "l"(src));
}
__device__ __forceinline__ void cp_commit() { asm volatile("cp.async.commit_group;"); }
template<int N> __device__ __forceinline__ void cp_wait() {
    asm volatile("cp.async.wait_group %0;" :: "n"(N) : "memory");
}
__device__ __forceinline__ u32 pack_h(float x, float y) {
    __half2 h = __floats2half2_rn(x, y);
    return *reinterpret_cast<u32*>(&h);
}
// plane byte offset: row n, half-col k; 256B rows, XOR swizzle on 16B chunks
__device__ __forceinline__ u32 plane_off(int n, int k) {
    int c = k >> 3;
    u32 sw = (u32)(((c ^ n) & 7) | (c & 8));
    return (u32)(n * 256) + (sw << 4) + (u32)((k & 7) * 2);
}
__device__ __forceinline__ void ldm4(u32* a, u32 addr) {
    asm volatile("ldmatrix.sync.aligned.m8n8.x4.shared.b16 {%0,%1,%2,%3}, [%4];"
        : "=r"(a[0]), "=r"(a[1]), "=r"(a[2]), "=r"(a[3]) : "r"(addr));
}
__device__ __forceinline__ void ldm2(u32* b, u32 addr) {
    asm volatile("ldmatrix.sync.aligned.m8n8.x2.shared.b16 {%0,%1}, [%2];"
        : "=r"(b[0]), "=r"(b[1]) : "r"(addr));
}
__device__ __forceinline__ void mma_h(float* d, const u32* a, const u32* b) {
    asm volatile("mma.sync.aligned.m16n8k16.row.col.f32.f16.f16.f32 "
        "{%0,%1,%2,%3}, {%4,%5,%6,%7}, {%8,%9}, {%0,%1,%2,%3};"
        : "+f"(d[0]), "+f"(d[1]), "+f"(d[2]), "+f"(d[3])
        : "r"(a[0]), "r"(a[1]), "r"(a[2]), "r"(a[3]), "r"(b[0]), "r"(b[1]));
}

// convert own-copied f32 chunks (RST, 64KB) -> fp16 plane (32KB). Each thread
// touches exactly the bytes it cp.async'd (tid*16 + 8192*j) => own-group wait only.
__device__ __forceinline__ void convert_own(u32 sb, u32 dst, int tid) {
#pragma unroll
    for (int j = 0; j < 8; j++) {
        int o = tid * 16 + 8192 * j;
        int m = o >> 9, c4 = (o & 511) >> 4;
        float4 v;
        asm volatile("ld.shared.v4.f32 {%0,%1,%2,%3}, [%4];"
            : "=f"(v.x), "=f"(v.y), "=f"(v.z), "=f"(v.w) : "r"(sb + RST + o));
        u32 h0 = pack_h(v.x, v.y);
        u32 h1 = pack_h(v.z, v.w);
        asm volatile("st.shared.v2.b32 [%0], {%1,%2};"
            :: "r"(dst + plane_off(m, c4 * 4)), "r"(h0), "r"(h1));
    }
}

// ============ warp GEMM: 32 M-rows (MF=2), NF n8-tiles, paired x4 B loads ============
template<int NF>
__device__ __forceinline__ void gemm2m(float C[2][NF][4], u32 ah, u32 bw,
                                       int m0, int tbase, int lane)
{
#pragma unroll
    for (int mf = 0; mf < 2; mf++)
#pragma unroll
        for (int j = 0; j < NF; j++)
#pragma unroll
            for (int i = 0; i < 4; i++) C[mf][j][i] = 0.f;

    const int rA = m0 + (lane & 7) + ((lane >> 3) & 1) * 8;
    const int gA = lane >> 4;
    const u32 oA = (u32)rA * 256;
    const int rBl = lane & 7;
    const int gB = (lane >> 3) & 1;
    const int tsel = (lane >> 4) & 1;

#pragma unroll
    for (int t = 0; t < 8; t++) {
        const int cA = 2 * t + gA;
        const u32 swA = ((u32)(((cA ^ rA) & 7) | (cA & 8))) << 4;
        u32 A0[4], A1[4];
        ldm4(A0, ah + oA + swA);            // rows m0..m0+15
        ldm4(A1, ah + oA + 4096 + swA);     // rows m0+16..m0+31

        const int cB = 2 * t + gB;
#pragma unroll
        for (int jp = 0; jp < NF / 2; jp++) {
            int tile = tbase + 2 * jp + tsel;
            int rB = tile * 8 + rBl;
            u32 swB = ((u32)(((cB ^ rB) & 7) | (cB & 8))) << 4;
            u32 B4[4];
            ldm4(B4, bw + (u32)rB * 256 + swB);
            mma_h(C[0][2 * jp],     A0, B4);
            mma_h(C[0][2 * jp + 1], A0, B4 + 2);
            mma_h(C[1][2 * jp],     A1, B4);
            mma_h(C[1][2 * jp + 1], A1, B4 + 2);
        }
        if (NF & 1) {
            int tile = tbase + NF - 1;
            int rB = tile * 8 + rBl;
            u32 swB = ((u32)(((cB ^ rB) & 7) | (cB & 8))) << 4;
            u32 B2[2];
            ldm2(B2, bw + (u32)rB * 256 + swB);
            mma_h(C[0][NF - 1], A0, B2);
            mma_h(C[1][NF - 1], A1, B2);
        }
    }
}

// ======================= L1 epilogue (activation stores to dst + aux) =======================
template<int NF, int TBASE>
__device__ __forceinline__ void epi_L1(float C[2][NF][4], u32 dst,
    const float* __restrict__ b1n, const float* __restrict__ bc1,
    const float* __restrict__ Wc2,
    float r_bs1, float r_Ws2, float r_bs2, float r_bc2,
    float* sG, float creg[4], int m0, int lane, int q)
{
    float cp[4] = {0.f, 0.f, 0.f, 0.f};
#pragma unroll
    for (int j = 0; j < NF; j++) {
        const int tile = TBASE + j;
        if (tile < 16) {
            int col = tile * 8 + q;
            float bx = __ldg(b1n + col), by = __ldg(b1n + col + 1);
#pragma unroll
            for (int mf = 0; mf < 2; mf++) {
                int row0 = m0 + mf * 16 + (lane >> 2), row8 = row0 + 8;
                u32 h0 = pack_h(fmaxf(C[mf][j][0] + bx, 0.f), fmaxf(C[mf][j][1] + by, 0.f));
                u32 h2 = pack_h(fmaxf(C[mf][j][2] + bx, 0.f), fmaxf(C[mf][j][3] + by, 0.f));
                u32 sw0 = ((u32)(((tile ^ row0) & 7) | (tile & 8))) << 4;
                u32 sw8 = ((u32)(((tile ^ row8) & 7) | (tile & 8))) << 4;
                asm volatile("st.shared.b32 [%0], %1;"
                    :: "r"(dst + (u32)row0 * 256 + sw0 + (u32)(q * 2)), "r"(h0));
                asm volatile("st.shared.b32 [%0], %1;"
                    :: "r"(dst + (u32)row8 * 256 + sw8 + (u32)(q * 2)), "r"(h2));
            }
        } else if (tile < 20) {     // constraint cols: e in [0,32)
            int e = (tile - 16) * 8 + q;
            float bb0 = __ldg(bc1 + e),  bb1 = __ldg(bc1 + e + 1);
            float w0  = __ldg(Wc2 + e),  w1  = __ldg(Wc2 + e + 1);
#pragma unroll
            for (int mf = 0; mf < 2; mf++) {
                cp[mf * 2 + 0] = fmaf(fmaxf(C[mf][j][0] + bb0, 0.f), w0,
                                 fmaf(fmaxf(C[mf][j][1] + bb1, 0.f), w1, cp[mf * 2 + 0]));
                cp[mf * 2 + 1] = fmaf(fmaxf(C[mf][j][2] + bb0, 0.f), w0,
                                 fmaf(fmaxf(C[mf][j][3] + bb1, 0.f), w1, cp[mf * 2 + 1]));
            }
        } else if (tile == 20) {    // gate col (e==32) at q==0
            if (q == 0) {
#pragma unroll
                for (int mf = 0; mf < 2; mf++) {
                    int row0 = m0 + mf * 16 + (lane >> 2), row8 = row0 + 8;
                    float s0 = fmaf(fmaxf(C[mf][j][0] + r_bs1, 0.f), r_Ws2, r_bs2);
                    float s8 = fmaf(fmaxf(C[mf][j][2] + r_bs1, 0.f), r_Ws2, r_bs2);
                    sG[row0] = 1.f / (1.f + __expf(-s0));
                    sG[row8] = 1.f / (1.f + __expf(-s8));
                }
            }
        }
        // tile 21: zero padding, skip
    }
    if (TBASE >= 12) {              // constraint-carrying warps (nw 2,3)
#pragma unroll
        for (int i = 0; i < 4; i++) {
            cp[i] += __shfl_xor_sync(0xffffffffu, cp[i], 1);
            cp[i] += __shfl_xor_sync(0xffffffffu, cp[i], 2);
        }
        if ((lane & 3) == 0) {
            float add = (TBASE == 12) ? r_bc2 : 0.f;
#pragma unroll
            for (int i = 0; i < 4; i++) creg[i] += cp[i] + add;
        }
    }
}

// ======================= prep kernel: fp32 weights -> swizzled fp16 =======================
extern "C" __global__ void __launch_bounds__(256)
prep_kernel(const float* __restrict__ W1, const float* __restrict__ W2,
            const float* __restrict__ W3, const float* __restrict__ Wc1,
            const float* __restrict__ Ws1)
{
    int idx = blockIdx.x * 256 + threadIdx.x;
    if (idx < 81920) {
        int agent = idx / 10240;
        int rem = idx % 10240;
        int row = rem >> 5;
        int k = (rem & 31) * 4;
        const float* src; int n, N; u32 loff;
        if (row < 128)      { src = W1 + agent * 16384; n = row;       N = 128; loff = 0; }
        else if (row < 256) { src = W2 + agent * 16384; n = row - 128; N = 128; loff = 32768; }
        else                { src = W3 + agent * 8192;  n = row - 256; N = 64;  loff = 65536; }
        u32 h0 = pack_h(src[(k + 0) * N + n], src[(k + 1) * N + n]);
        u32 h1 = pack_h(src[(k + 2) * N + n], src[(k + 3) * N + n]);
        *(uint2*)(g_w + (u32)agent * 81920 + loff + plane_off(n, k)) = make_uint2(h0, h1);
    } else if (idx < 81920 + 1536) {
        int rem = idx - 81920;
        int row = rem >> 5;
        int k = (rem & 31) * 4;
        float w[4];
#pragma unroll
        for (int i = 0; i < 4; i++) {
            int kk = k + i;
            w[i] = (row < 32) ? __ldg(Wc1 + kk * 32 + row) : (row == 32 ? __ldg(Ws1 + kk) : 0.f);
        }
        *(uint2*)(g_ax + plane_off(row, k)) =
            make_uint2(pack_h(w[0], w[1]), pack_h(w[2], w[3]));
    }
}

// ======================= main kernel (one 512-thread CTA per SM) =======================
extern "C" __global__ void __launch_bounds__(512, 1)
qatten_mma(const float* __restrict__ states,
           const float* __restrict__ b1, const float* __restrict__ b2,
           const float* __restrict__ b3,
           const float* __restrict__ bs1, const float* __restrict__ Ws2,
           const float* __restrict__ bs2,
           const float* __restrict__ bc1, const float* __restrict__ Wc2,
           const float* __restrict__ bc2,
           float* __restrict__ out)
{
    extern __shared__ char smem[];
    const u32 sb = smem_u32(smem);
    const int tid = threadIdx.x;
    const int wid = tid >> 5, lane = tid & 31;
    const int b0 = blockIdx.x * BM;

    const int mq = wid & 3, nw = wid >> 2;   // 4 M-slices x 4 N-slices
    const int m0 = mq * 32;
    const int q = (lane & 3) * 2;

    float* sG  = (float*)(smem + SGOFF);
    float* sRd = (float*)(smem + SREDO);

    // ---- prologue: stage states(0) -> RST; W1(0)+aux -> RW; convert(0) -> P0 ----
    {
        const unsigned char* S0 = (const unsigned char*)(states + (size_t)b0 * 128);
        for (int i = tid * 16; i < 65536; i += 8192) cp16(sb + RST + i, S0 + i);
        cp_commit();                                        // [S]
        for (int i = tid * 16; i < 32768; i += 8192) cp16(sb + RW + i, g_w + i);
        for (int i = tid * 16; i < 12288; i += 8192) cp16(sb + RW + 32768 + i, g_ax + i);
        cp_commit();                                        // [S, W1]
        cp_wait<1>();                // own states chunks done (W1 outstanding)
        convert_own(sb, sb + RA, tid);   // states(0) -> P0
    }

    float oacc[2][2][4];
#pragma unroll
    for (int mf = 0; mf < 2; mf++)
#pragma unroll
        for (int j = 0; j < 2; j++)
#pragma unroll
            for (int i = 0; i < 4; i++) oacc[mf][j][i] = 0.f;
    float creg[4] = {0.f, 0.f, 0.f, 0.f};
    const float r_bs1 = __ldg(bs1), r_Ws2 = __ldg(Ws2), r_bs2 = __ldg(bs2), r_bc2 = __ldg(bc2);

    for (int n = 0; n < NAGENT; n++) {
        const u32 pin  = sb + ((n & 1) ? RB : RA);   // L1 input (states), L2 output, L3 input
        const u32 pmid = sb + ((n & 1) ? RA : RB);   // L1 output, L2 input, convert(n+1) dest

        // ---- L1 phase: weights ready + all prior smem writes visible ----
        cp_wait<0>();
        __syncthreads();
        {
            const float* b1n = b1 + n * 128;
            if (nw < 2) {
                float C[2][6][4];
                gemm2m<6>(C, pin, sb + RW, m0, nw * 6, lane);
                __syncthreads();    // pin + RW consumed
                {   // stream W2 while epilogue runs
                    const unsigned char* src = g_w + (size_t)n * 81920 + 32768;
                    for (int i = tid * 16; i < 32768; i += 8192) cp16(sb + RW + i, src + i);
                    cp_commit();    // [W2]
                }
                if (nw == 0)
                    epi_L1<6, 0>(C, pmid, b1n, bc1, Wc2, r_bs1, r_Ws2, r_bs2, r_bc2,
                                 sG, creg, m0, lane, q);
                else
                    epi_L1<6, 6>(C, pmid, b1n, bc1, Wc2, r_bs1, r_Ws2, r_bs2, r_bc2,
                                 sG, creg, m0, lane, q);
            } else {
                float C[2][5][4];
                gemm2m<5>(C, pin, sb + RW, m0, (nw == 2) ? 12 : 17, lane);
                __syncthreads();
                {
                    const unsigned char* src = g_w + (size_t)n * 81920 + 32768;
                    for (int i = tid * 16; i < 32768; i += 8192) cp16(sb + RW + i, src + i);
                    cp_commit();    // [W2]
                }
                if (nw == 2)
                    epi_L1<5, 12>(C, pmid, b1n, bc1, Wc2, r_bs1, r_Ws2, r_bs2, r_bc2,
                                  sG, creg, m0, lane, q);
                else
                    epi_L1<5, 17>(C, pmid, b1n, bc1, Wc2, r_bs1, r_Ws2, r_bs2, r_bc2,
                                  sG, creg, m0, lane, q);
            }
        }
        cp_wait<0>();
        __syncthreads();

        // ---- L2: pmid @ W2 -> pin ----
        {
            float C[2][4][4];
            gemm2m<4>(C, pmid, sb + RW, m0, nw * 4, lane);
            __syncthreads();        // pmid + RW consumed
            {   // stream W3 + states(n+1)
                const unsigned char* src = g_w + (size_t)n * 81920 + 65536;
                for (int i = tid * 16; i < 16384; i += 8192) cp16(sb + RW + i, src + i);
                cp_commit();        // [W3]
                if (n < NAGENT - 1) {
                    const unsigned char* Sn =
                        (const unsigned char*)(states + ((size_t)(n + 1) * BATCH + b0) * 128);
                    for (int i = tid * 16; i < 65536; i += 8192) cp16(sb + RST + i, Sn + i);
                }
                cp_commit();        // [W3, S'] (S' empty at n=7; keeps group count)
            }
            const float* b2n = b2 + n * 128;
#pragma unroll
            for (int j = 0; j < 4; j++) {
                int tile = nw * 4 + j;
                int col = tile * 8 + q;
                float bx = __ldg(b2n + col), by = __ldg(b2n + col + 1);
#pragma unroll
                for (int mf = 0; mf < 2; mf++) {
                    int row0 = m0 + mf * 16 + (lane >> 2), row8 = row0 + 8;
                    u32 h0 = pack_h(fmaxf(C[mf][j][0] + bx, 0.f), fmaxf(C[mf][j][1] + by, 0.f));
                    u32 h2 = pack_h(fmaxf(C[mf][j][2] + bx, 0.f), fmaxf(C[mf][j][3] + by, 0.f));
                    u32 sw0 = ((u32)(((tile ^ row0) & 7) | (tile & 8))) << 4;
                    u32 sw8 = ((u32)(((tile ^ row8) & 7) | (tile & 8))) << 4;
                    asm volatile("st.shared.b32 [%0], %1;"
                        :: "r"(pin + (u32)row0 * 256 + sw0 + (u32)(q * 2)), "r"(h0));
                    asm volatile("st.shared.b32 [%0], %1;"
                        :: "r"(pin + (u32)row8 * 256 + sw8 + (u32)(q * 2)), "r"(h2));
                }
            }
        }
        cp_wait<1>();               // W3 ready (S' may be outstanding)
        __syncthreads();

        // ---- L3: pin @ W3 -> oacc ; convert(n+1) -> pmid hides under the gemm ----
        {
            float C[2][2][4];
            gemm2m<2>(C, pin, sb + RW, m0, nw * 2, lane);
            if (n < NAGENT - 1) {
                cp_wait<0>();               // own states(n+1) chunks done
                convert_own(sb, pmid, tid); // pmid free (L2 consumed it)
            }
            const float* b3n = b3 + n * 64;
#pragma unroll
            for (int mf = 0; mf < 2; mf++) {
                int row0 = m0 + mf * 16 + (lane >> 2), row8 = row0 + 8;
                float g0 = sG[row0], g8 = sG[row8];
#pragma unroll
                for (int j = 0; j < 2; j++) {
                    int col = (nw * 2 + j) * 8 + q;
                    float bx = __ldg(b3n + col), by = __ldg(b3n + col + 1);
                    oacc[mf][j][0] = fmaf(g0, C[mf][j][0] + bx, oacc[mf][j][0]);
                    oacc[mf][j][1] = fmaf(g0, C[mf][j][1] + by, oacc[mf][j][1]);
                    oacc[mf][j][2] = fmaf(g8, C[mf][j][2] + bx, oacc[mf][j][2]);
                    oacc[mf][j][3] = fmaf(g8, C[mf][j][3] + by, oacc[mf][j][3]);
                }
            }
            __syncthreads();        // pin + RW consumed; convert visible
            if (n < NAGENT - 1) {   // stream W1(n+1) (aux rows persist)
                const unsigned char* src = g_w + (size_t)(n + 1) * 81920;
                for (int i = tid * 16; i < 32768; i += 8192) cp16(sb + RW + i, src + i);
                cp_commit();        // [W1']
            }
        }
    }

    // ---- final: csum exchange + output ----
    if ((nw == 2 || nw == 3) && (lane & 3) == 0) {
        int slot = nw - 2;
#pragma unroll
        for (int i = 0; i < 4; i++) {
            int row = m0 + (i >> 1) * 16 + (i & 1) * 8 + (lane >> 2);
            sRd[row * 2 + slot] = creg[i];
        }
    }
    __syncthreads();
#pragma unroll
    for (int mf = 0; mf < 2; mf++) {
#pragma unroll
        for (int h = 0; h < 2; h++) {
            int row = m0 + mf * 16 + h * 8 + (lane >> 2);
            float cs = (sRd[row * 2] + sRd[row * 2 + 1]) * 0.125f;
#pragma unroll
            for (int j = 0; j < 2; j++) {
                int col = (nw * 2 + j) * 8 + q;
                float2 v;
                v.x = fmaf(oacc[mf][j][2 * h + 0], 0.125f, cs);
                v.y = fmaf(oacc[mf][j][2 * h + 1], 0.125f, cs);
                *(float2*)(out + (size_t)(b0 + row) * 64 + col) = v;
            }
        }
    }
}

extern "C" void kernel_launch(void* const* d_in, const int* in_sizes, int n_in,
                              void* d_out, int out_size)
{
    const float* states = (const float*)d_in[0];
    const float* W1  = (const float*)d_in[1];
    const float* b1  = (const float*)d_in[2];
    const float* W2  = (const float*)d_in[3];
    const float* b2  = (const float*)d_in[4];
    const float* W3  = (const float*)d_in[5];
    const float* b3  = (const float*)d_in[6];
    // d_in[7..12]: Wq1,bq1,Wq2,bq2,Wk,bk — dead (softmax rows sum to 1)
    const float* Ws1 = (const float*)d_in[13];
    const float* bs1 = (const float*)d_in[14];
    const float* Ws2 = (const float*)d_in[15];
    const float* bs2 = (const float*)d_in[16];
    const float* Wc1 = (const float*)d_in[17];
    const float* bc1 = (const float*)d_in[18];
    const float* Wc2 = (const float*)d_in[19];
    const float* bc2 = (const float*)d_in[20];
    float* out = (float*)d_out;

    prep_kernel<<<(81920 + 1536 + 255) / 256, 256>>>(W1, W2, W3, Wc1, Ws1);

    cudaFuncSetAttribute(qatten_mma,
                         cudaFuncAttributeMaxDynamicSharedMemorySize, SMEM_TOTAL);
    qatten_mma<<<BATCH / BM, 512, SMEM_TOTAL>>>(
        states, b1, b2, b3, bs1, Ws2, bs2, bc1, Wc2, bc2, out);
}